// round 2
// baseline (speedup 1.0000x reference)
#include <cuda_runtime.h>

#define N_COLS   32
#define CAT_DIM  2000
#define TOTAL    64000
#define HIDDEN   128
#define MAX_B    2048

// Scratch (device globals — no allocation allowed in kernel_launch).
__device__ float g_WT[(size_t)TOTAL * HIDDEN];   // W_enc transposed: [vocab, hidden]
__device__ float g_y[(size_t)MAX_B * HIDDEN];    // sigmoid activations

// ---------------------------------------------------------------------------
// 1) Transpose W_enc [HIDDEN, TOTAL] -> g_WT [TOTAL, HIDDEN] (coalesced both sides)
// ---------------------------------------------------------------------------
__global__ void transpose_kernel(const float* __restrict__ W) {
    __shared__ float tile[32][33];
    int v = blockIdx.x * 32 + threadIdx.x;   // vocab index (input col)
    int h = blockIdx.y * 32 + threadIdx.y;   // hidden index (input row)
    #pragma unroll
    for (int j = 0; j < 32; j += 8)
        tile[threadIdx.y + j][threadIdx.x] = W[(size_t)(h + j) * TOTAL + v];
    __syncthreads();
    int h2 = blockIdx.y * 32 + threadIdx.x;
    int v2 = blockIdx.x * 32 + threadIdx.y;
    #pragma unroll
    for (int j = 0; j < 32; j += 8)
        g_WT[(size_t)(v2 + j) * HIDDEN + h2] = tile[threadIdx.x][threadIdx.y + j];
}

// ---------------------------------------------------------------------------
// 2) Encode: y[b,h] = sigmoid(b_enc[h] + sum_i WT[x_cat[b,i] + i*2000, h])
//    One block per batch row, 128 threads (one per hidden unit). Coalesced.
// ---------------------------------------------------------------------------
__global__ void encode_kernel(const int* __restrict__ x_cat,
                              const float* __restrict__ b_enc,
                              float* __restrict__ y_out) {
    int b = blockIdx.x;
    int h = threadIdx.x;
    __shared__ int gidx[N_COLS];
    if (h < N_COLS) gidx[h] = x_cat[b * N_COLS + h] + h * CAT_DIM;
    __syncthreads();
    float acc = b_enc[h];
    #pragma unroll
    for (int i = 0; i < N_COLS; i++)
        acc += g_WT[(size_t)gidx[i] * HIDDEN + h];
    float s = 1.0f / (1.0f + expf(-acc));
    g_y[(size_t)b * HIDDEN + h] = s;
    if (y_out) y_out[(size_t)b * HIDDEN + h] = s;
}

// ---------------------------------------------------------------------------
// 3) Decode GEMM: z[b,v] = sum_k y[b,k] * W_dec[v,k] + b_dec[v]
//    M=batch, N=64000, K=128. Classic register-blocked SGEMM:
//    128x128 block tile, BK=16, 256 threads, 8x8 per-thread micro-tile.
// ---------------------------------------------------------------------------
#define BM 128
#define BN 128
#define BK 16
#define PAD 4   // keeps rows 16B-aligned AND breaks the worst bank conflicts

__global__ __launch_bounds__(256, 2)
void decode_gemm(const float* __restrict__ Wd,
                 const float* __restrict__ bias,
                 float* __restrict__ C) {
    __shared__ float As[BK][BM + PAD];
    __shared__ float Bs[BK][BN + PAD];

    const int m0 = blockIdx.y * BM;
    const int v0 = blockIdx.x * BN;
    const int tid = threadIdx.x;
    const int tr = tid >> 4;       // 0..15 (row group)
    const int tc = tid & 15;       // 0..15 (col group)

    float acc[8][8];
    #pragma unroll
    for (int i = 0; i < 8; i++)
        #pragma unroll
        for (int j = 0; j < 8; j++)
            acc[i][j] = 0.0f;

    for (int kc = 0; kc < HIDDEN; kc += BK) {
        // Cooperative load: A tile (128m x 16k) and B tile (128v x 16k),
        // both transposed into smem as [k][m] / [k][v]. float4 global loads.
        #pragma unroll
        for (int it = 0; it < 2; it++) {
            int idx = tid + it * 256;
            int r  = idx >> 2;       // 0..127
            int k4 = idx & 3;        // which float4 along k
            float4 av = *(const float4*)&g_y[(size_t)(m0 + r) * HIDDEN + kc + k4 * 4];
            As[k4 * 4 + 0][r] = av.x;
            As[k4 * 4 + 1][r] = av.y;
            As[k4 * 4 + 2][r] = av.z;
            As[k4 * 4 + 3][r] = av.w;
            float4 bv = *(const float4*)&Wd[(size_t)(v0 + r) * HIDDEN + kc + k4 * 4];
            Bs[k4 * 4 + 0][r] = bv.x;
            Bs[k4 * 4 + 1][r] = bv.y;
            Bs[k4 * 4 + 2][r] = bv.z;
            Bs[k4 * 4 + 3][r] = bv.w;
        }
        __syncthreads();

        #pragma unroll
        for (int k = 0; k < BK; k++) {
            float a[8], b[8];
            #pragma unroll
            for (int i = 0; i < 8; i++) a[i] = As[k][tr * 8 + i];
            #pragma unroll
            for (int j = 0; j < 8; j++) b[j] = Bs[k][tc * 8 + j];
            #pragma unroll
            for (int i = 0; i < 8; i++)
                #pragma unroll
                for (int j = 0; j < 8; j++)
                    acc[i][j] = fmaf(a[i], b[j], acc[i][j]);
        }
        __syncthreads();
    }

    // Epilogue: add bias, vectorized stores.
    #pragma unroll
    for (int i = 0; i < 8; i++) {
        size_t row = (size_t)(m0 + tr * 8 + i) * TOTAL + v0 + tc * 8;
        #pragma unroll
        for (int j = 0; j < 8; j += 4) {
            float4 bv = *(const float4*)&bias[v0 + tc * 8 + j];
            float4 o;
            o.x = acc[i][j + 0] + bv.x;
            o.y = acc[i][j + 1] + bv.y;
            o.z = acc[i][j + 2] + bv.z;
            o.w = acc[i][j + 3] + bv.w;
            *(float4*)&C[row + j] = o;
        }
    }
}

// ---------------------------------------------------------------------------
// Launch
// ---------------------------------------------------------------------------
extern "C" void kernel_launch(void* const* d_in, const int* in_sizes, int n_in,
                              void* d_out, int out_size) {
    const int*   x_cat = (const int*)d_in[0];
    // d_in[1] = W_enc (transposed in-kernel), d_in[2] = b_enc
    const float* W_enc = (const float*)d_in[1];
    const float* b_enc = (const float*)d_in[2];
    const float* W_dec = (const float*)d_in[3];
    const float* b_dec = (const float*)d_in[4];

    int B = in_sizes[0] / N_COLS;
    if (B > MAX_B) B = MAX_B;

    float* out = (float*)d_out;
    size_t yElems = (size_t)B * HIDDEN;
    size_t zElems = (size_t)B * TOTAL;

    // Tuple output (y, z_raw) is flattened+concatenated in return order.
    float* yOut;
    float* zOut;
    if ((long long)out_size == (long long)(yElems + zElems)) {
        yOut = out;
        zOut = out + yElems;
    } else {
        yOut = nullptr;   // output holds only z_raw
        zOut = out;
    }

    // 1) Transpose W_enc into g_WT
    transpose_kernel<<<dim3(TOTAL / 32, HIDDEN / 32), dim3(32, 8)>>>(W_enc);

    // 2) Encode (gather-sum + sigmoid)
    encode_kernel<<<B, HIDDEN>>>(x_cat, b_enc, yOut);

    // 3) Decode GEMM + bias
    decode_gemm<<<dim3(TOTAL / BN, (B + BM - 1) / BM), 256>>>(W_dec, b_dec, zOut);
}

// round 4
// speedup vs baseline: 2.3906x; 2.3906x over previous
#include <cuda_runtime.h>
#include <cuda_bf16.h>
#include <cstdint>

#define N_COLS   32
#define CAT_DIM  2000
#define TOTAL    64000
#define HIDDEN   128
#define MAX_B    2048

// -------- device scratch (no allocations allowed) --------
__device__ float          g_WT[(size_t)TOTAL * HIDDEN];     // W_enc^T for coalesced gathers
__device__ __nv_bfloat16  g_Wd_hi[(size_t)TOTAL * HIDDEN];  // W_dec split bf16 high
__device__ __nv_bfloat16  g_Wd_lo[(size_t)TOTAL * HIDDEN];  // W_dec split bf16 low
__device__ __nv_bfloat16  g_y_hi[(size_t)MAX_B * HIDDEN];   // sigmoid(y) split
__device__ __nv_bfloat16  g_y_lo[(size_t)MAX_B * HIDDEN];

// ---------------------------------------------------------------------------
// 1) Transpose W_enc [HIDDEN, TOTAL] -> g_WT [TOTAL, HIDDEN]
// ---------------------------------------------------------------------------
__global__ void transpose_kernel(const float* __restrict__ W) {
    __shared__ float tile[32][33];
    int v = blockIdx.x * 32 + threadIdx.x;
    int h = blockIdx.y * 32 + threadIdx.y;
    #pragma unroll
    for (int j = 0; j < 32; j += 8)
        tile[threadIdx.y + j][threadIdx.x] = W[(size_t)(h + j) * TOTAL + v];
    __syncthreads();
    int h2 = blockIdx.y * 32 + threadIdx.x;
    int v2 = blockIdx.x * 32 + threadIdx.y;
    #pragma unroll
    for (int j = 0; j < 32; j += 8)
        g_WT[(size_t)(v2 + j) * HIDDEN + h2] = tile[threadIdx.x][threadIdx.y + j];
}

// ---------------------------------------------------------------------------
// 2) Split W_dec fp32 -> (hi, lo) bf16 pair. float4 vectorized.
// ---------------------------------------------------------------------------
__global__ void convert_wdec(const float4* __restrict__ Wd) {
    size_t i = (size_t)blockIdx.x * blockDim.x + threadIdx.x;
    float4 w = Wd[i];
    __nv_bfloat16 h0 = __float2bfloat16(w.x), h1 = __float2bfloat16(w.y);
    __nv_bfloat16 h2 = __float2bfloat16(w.z), h3 = __float2bfloat16(w.w);
    __nv_bfloat16 l0 = __float2bfloat16(w.x - __bfloat162float(h0));
    __nv_bfloat16 l1 = __float2bfloat16(w.y - __bfloat162float(h1));
    __nv_bfloat16 l2 = __float2bfloat16(w.z - __bfloat162float(h2));
    __nv_bfloat16 l3 = __float2bfloat16(w.w - __bfloat162float(h3));
    __nv_bfloat162* hi2 = (__nv_bfloat162*)g_Wd_hi;
    __nv_bfloat162* lo2 = (__nv_bfloat162*)g_Wd_lo;
    hi2[i * 2 + 0] = __nv_bfloat162(h0, h1);
    hi2[i * 2 + 1] = __nv_bfloat162(h2, h3);
    lo2[i * 2 + 0] = __nv_bfloat162(l0, l1);
    lo2[i * 2 + 1] = __nv_bfloat162(l2, l3);
}

// ---------------------------------------------------------------------------
// 3) Encode: gather-sum + sigmoid; emit y (fp32 out) and split bf16 copies.
// ---------------------------------------------------------------------------
__global__ void encode_kernel(const int* __restrict__ x_cat,
                              const float* __restrict__ b_enc,
                              float* __restrict__ y_out) {
    int b = blockIdx.x;
    int h = threadIdx.x;
    __shared__ int gidx[N_COLS];
    if (h < N_COLS) gidx[h] = x_cat[b * N_COLS + h] + h * CAT_DIM;
    __syncthreads();
    float acc = b_enc[h];
    #pragma unroll
    for (int i = 0; i < N_COLS; i++)
        acc += g_WT[(size_t)gidx[i] * HIDDEN + h];
    float s = 1.0f / (1.0f + expf(-acc));
    if (y_out) y_out[(size_t)b * HIDDEN + h] = s;
    __nv_bfloat16 hi = __float2bfloat16(s);
    g_y_hi[(size_t)b * HIDDEN + h] = hi;
    g_y_lo[(size_t)b * HIDDEN + h] = __float2bfloat16(s - __bfloat162float(hi));
}

// ---------------------------------------------------------------------------
// 4) Decode GEMM via mma.sync m16n8k16 bf16 (3 accumulating passes).
//    CTA tile 128m x 128n, K=128 fully resident; 8 warps = 2(M) x 4(N),
//    warp tile 64x32. A double-buffered with cp.async across M-tiles.
// ---------------------------------------------------------------------------
#define GM 128
#define GN 128

#define OFF_BIAS   0
#define OFF_B_HI   1024
#define OFF_B_LO   (OFF_B_HI + 32768)
#define OFF_A0_HI  (OFF_B_LO + 32768)
#define OFF_A0_LO  (OFF_A0_HI + 32768)
#define OFF_A1_HI  (OFF_A0_LO + 32768)
#define OFF_A1_LO  (OFF_A1_HI + 32768)
#define SMEM_END   (OFF_A1_LO + 32768)
#define SMEM_NEED  (SMEM_END + 1024)

__device__ __forceinline__ uint32_t smem_u32(const void* p) {
    return (uint32_t)__cvta_generic_to_shared(p);
}
// Blocked-atom SW128 byte offset within a [128 rows x 128 k bf16] tile.
// atom = 8 rows x 64 bf16 (1024B); atoms tiled 16 (rows) x 2 (k).
__device__ __forceinline__ uint32_t tile_off(int r, int i /*16B chunk 0..15*/) {
    uint32_t off = (uint32_t)(((r >> 3) + ((i >> 3) << 4)) << 10)
                 + (uint32_t)((r & 7) << 7) + (uint32_t)((i & 7) << 4);
    return off ^ ((off >> 3) & 0x70);
}

__device__ __forceinline__ void cp16(uint32_t dst, const void* src) {
    asm volatile("cp.async.cg.shared.global [%0], [%1], 16;"
                 :: "r"(dst), "l"(src) : "memory");
}
__device__ __forceinline__ void ldsm_x4(uint32_t* f, uint32_t addr) {
    asm volatile("ldmatrix.sync.aligned.m8n8.x4.shared.b16 {%0,%1,%2,%3}, [%4];"
                 : "=r"(f[0]), "=r"(f[1]), "=r"(f[2]), "=r"(f[3]) : "r"(addr));
}
__device__ __forceinline__ void mma_bf16(float* c, const uint32_t* a, const uint32_t* b) {
    asm volatile(
        "mma.sync.aligned.m16n8k16.row.col.f32.bf16.bf16.f32 "
        "{%0,%1,%2,%3}, {%4,%5,%6,%7}, {%8,%9}, {%0,%1,%2,%3};"
        : "+f"(c[0]), "+f"(c[1]), "+f"(c[2]), "+f"(c[3])
        : "r"(a[0]), "r"(a[1]), "r"(a[2]), "r"(a[3]), "r"(b[0]), "r"(b[1]));
}

__global__ __launch_bounds__(256, 1)
void decode_gemm_mma(const float* __restrict__ bias, float* __restrict__ C,
                     int mBlocks) {
    extern __shared__ char smem_raw[];
    uint32_t raw = smem_u32(smem_raw);
    uint32_t base = (raw + 1023u) & ~1023u;
    char* sm = smem_raw + (base - raw);

    const int tid = threadIdx.x;
    const int wid = tid >> 5, lane = tid & 31;
    const int warpM = wid >> 2;          // 0..1
    const int warpN = wid & 3;           // 0..3
    const int v0 = blockIdx.x * GN;
    const int mPer = mBlocks / gridDim.y;
    const int mBeg = blockIdx.y * mPer;

    // bias stage
    if (tid < GN) *(float*)(sm + OFF_BIAS + tid * 4) = bias[v0 + tid];

    // B tile (hi+lo), swizzled, regular stores (once per CTA)
    #pragma unroll
    for (int it = 0; it < 8; it++) {
        int idx = it * 256 + tid;
        int r = idx >> 4, i = idx & 15;
        uint32_t so = tile_off(r, i);
        *(uint4*)(sm + OFF_B_HI + so) = ((const uint4*)(g_Wd_hi + (size_t)(v0 + r) * HIDDEN))[i];
        *(uint4*)(sm + OFF_B_LO + so) = ((const uint4*)(g_Wd_lo + (size_t)(v0 + r) * HIDDEN))[i];
    }

    // prefetch A tile 0 into buffer 0 (cp.async)
    {
        const int m0 = mBeg * GM;
        #pragma unroll
        for (int it = 0; it < 8; it++) {
            int idx = it * 256 + tid;
            int r = idx >> 4, i = idx & 15;
            uint32_t so = tile_off(r, i);
            cp16(base + OFF_A0_HI + so, (const char*)(g_y_hi + (size_t)(m0 + r) * HIDDEN) + i * 16);
            cp16(base + OFF_A0_LO + so, (const char*)(g_y_lo + (size_t)(m0 + r) * HIDDEN) + i * 16);
        }
        asm volatile("cp.async.commit_group;" ::: "memory");
    }

    // per-thread ldmatrix base addresses (row / chunk patterns)
    const int aRow = warpM * 64 + (lane & 15);            // + mt*16
    const int aChk = (lane >> 4);                         // + ks*2
    const int bRow = warpN * 32 + ((lane >> 4) << 3) + (lane & 7);  // + bt*16
    const int bChk = (lane >> 3) & 1;                     // + ks*2

    const uint32_t AOFF[2][2] = {{base + OFF_A0_HI, base + OFF_A0_LO},
                                 {base + OFF_A1_HI, base + OFF_A1_LO}};

    for (int mi = 0; mi < mPer; mi++) {
        const int m0 = (mBeg + mi) * GM;
        const int buf = mi & 1;

        asm volatile("cp.async.wait_group 0;" ::: "memory");
        __syncthreads();

        // prefetch next A tile into the other buffer
        if (mi + 1 < mPer) {
            const int m1 = (mBeg + mi + 1) * GM;
            const uint32_t hiDst = AOFF[buf ^ 1][0], loDst = AOFF[buf ^ 1][1];
            #pragma unroll
            for (int it = 0; it < 8; it++) {
                int idx = it * 256 + tid;
                int r = idx >> 4, i = idx & 15;
                uint32_t so = tile_off(r, i);
                cp16(hiDst + so, (const char*)(g_y_hi + (size_t)(m1 + r) * HIDDEN) + i * 16);
                cp16(loDst + so, (const char*)(g_y_lo + (size_t)(m1 + r) * HIDDEN) + i * 16);
            }
            asm volatile("cp.async.commit_group;" ::: "memory");
        }

        float acc[4][4][4];
        #pragma unroll
        for (int mt = 0; mt < 4; mt++)
            #pragma unroll
            for (int nt = 0; nt < 4; nt++)
                #pragma unroll
                for (int q = 0; q < 4; q++)
                    acc[mt][nt][q] = 0.0f;

        const uint32_t aHi = AOFF[buf][0], aLo = AOFF[buf][1];

        #pragma unroll
        for (int ks = 0; ks < 8; ks++) {
            uint32_t ah[4][4], al[4][4];
            #pragma unroll
            for (int mt = 0; mt < 4; mt++) {
                uint32_t so = tile_off(aRow + mt * 16, ks * 2 + aChk);
                ldsm_x4(ah[mt], aHi + so);
                ldsm_x4(al[mt], aLo + so);
            }
            uint32_t bh[4][2], bl[4][2];
            #pragma unroll
            for (int bt = 0; bt < 2; bt++) {
                uint32_t so = tile_off(bRow + bt * 16, ks * 2 + bChk);
                uint32_t fh[4], fl[4];
                ldsm_x4(fh, base + OFF_B_HI + so);
                ldsm_x4(fl, base + OFF_B_LO + so);
                bh[bt * 2 + 0][0] = fh[0]; bh[bt * 2 + 0][1] = fh[1];
                bh[bt * 2 + 1][0] = fh[2]; bh[bt * 2 + 1][1] = fh[3];
                bl[bt * 2 + 0][0] = fl[0]; bl[bt * 2 + 0][1] = fl[1];
                bl[bt * 2 + 1][0] = fl[2]; bl[bt * 2 + 1][1] = fl[3];
            }
            #pragma unroll
            for (int mt = 0; mt < 4; mt++)
                #pragma unroll
                for (int nt = 0; nt < 4; nt++) {
                    mma_bf16(acc[mt][nt], ah[mt], bh[nt]);
                    mma_bf16(acc[mt][nt], al[mt], bh[nt]);
                    mma_bf16(acc[mt][nt], ah[mt], bl[nt]);
                }
        }

        // epilogue: bias + float2 stores (4 threads per 32B sector)
        const int cCol = warpN * 32 + 2 * (lane & 3);
        const int cRow = warpM * 64 + (lane >> 2);
        #pragma unroll
        for (int mt = 0; mt < 4; mt++) {
            #pragma unroll
            for (int nt = 0; nt < 4; nt++) {
                int col = cCol + nt * 8;
                float bx = *(float*)(sm + OFF_BIAS + col * 4);
                float by = *(float*)(sm + OFF_BIAS + (col + 1) * 4);
                size_t r0 = (size_t)(m0 + cRow + mt * 16) * TOTAL + v0 + col;
                size_t r1 = r0 + 8 * TOTAL;
                float2 o0 = make_float2(acc[mt][nt][0] + bx, acc[mt][nt][1] + by);
                float2 o1 = make_float2(acc[mt][nt][2] + bx, acc[mt][nt][3] + by);
                *(float2*)&C[r0] = o0;
                *(float2*)&C[r1] = o1;
            }
        }
        __syncthreads();   // protect smem A buffer reuse ordering
    }
}

// ---------------------------------------------------------------------------
// Launch
// ---------------------------------------------------------------------------
extern "C" void kernel_launch(void* const* d_in, const int* in_sizes, int n_in,
                              void* d_out, int out_size) {
    const int*   x_cat = (const int*)d_in[0];
    const float* W_enc = (const float*)d_in[1];
    const float* b_enc = (const float*)d_in[2];
    const float* W_dec = (const float*)d_in[3];
    const float* b_dec = (const float*)d_in[4];

    int B = in_sizes[0] / N_COLS;
    if (B > MAX_B) B = MAX_B;

    float* out = (float*)d_out;
    size_t yElems = (size_t)B * HIDDEN;
    size_t zElems = (size_t)B * TOTAL;
    float* yOut;
    float* zOut;
    if ((long long)out_size == (long long)(yElems + zElems)) {
        yOut = out; zOut = out + yElems;
    } else {
        yOut = nullptr; zOut = out;
    }

    cudaFuncSetAttribute(decode_gemm_mma, cudaFuncAttributeMaxDynamicSharedMemorySize, SMEM_NEED);

    transpose_kernel<<<dim3(TOTAL / 32, HIDDEN / 32), dim3(32, 8)>>>(W_enc);
    convert_wdec<<<(TOTAL * HIDDEN / 4) / 256, 256>>>((const float4*)W_dec);
    encode_kernel<<<B, HIDDEN>>>(x_cat, b_enc, yOut);

    int mBlocks = B / GM;                       // 16
    int ySplit = (mBlocks % 2 == 0) ? 2 : 1;    // 1000 CTAs
    decode_gemm_mma<<<dim3(TOTAL / GN, ySplit), 256, SMEM_NEED>>>(b_dec, zOut, mBlocks);
}

// round 5
// speedup vs baseline: 2.6138x; 1.0934x over previous
#include <cuda_runtime.h>
#include <cuda_bf16.h>
#include <cstdint>

#define N_COLS   32
#define CAT_DIM  2000
#define TOTAL    64000
#define HIDDEN   128
#define MAX_B    2048

// -------- device scratch (no allocations allowed) --------
__device__ float          g_WT[(size_t)TOTAL * HIDDEN];     // W_enc^T for coalesced gathers
__device__ __nv_bfloat16  g_Wd_hi[(size_t)TOTAL * HIDDEN];  // W_dec split bf16 high
__device__ __nv_bfloat16  g_Wd_lo[(size_t)TOTAL * HIDDEN];  // W_dec split bf16 low
__device__ __nv_bfloat16  g_y_hi[(size_t)MAX_B * HIDDEN];   // sigmoid(y) split
__device__ __nv_bfloat16  g_y_lo[(size_t)MAX_B * HIDDEN];

// ---------------------------------------------------------------------------
// 1) Fused prep: blocks [0,8000) transpose W_enc -> g_WT;
//    blocks [8000,16000) split W_dec fp32 -> bf16 (hi,lo).
//    Both are bandwidth-bound; fusing overlaps their DRAM traffic.
// ---------------------------------------------------------------------------
__global__ void prep_kernel(const float* __restrict__ W,
                            const float4* __restrict__ Wd) {
    if (blockIdx.x < 8000) {
        __shared__ float tile[32][33];
        int bx = blockIdx.x % 2000, by = blockIdx.x / 2000;
        int tx = threadIdx.x & 31, ty = threadIdx.x >> 5;   // 32 x 8
        int v = bx * 32 + tx;
        int h = by * 32 + ty;
        #pragma unroll
        for (int j = 0; j < 32; j += 8)
            tile[ty + j][tx] = W[(size_t)(h + j) * TOTAL + v];
        __syncthreads();
        int h2 = by * 32 + tx;
        int v2 = bx * 32 + ty;
        #pragma unroll
        for (int j = 0; j < 32; j += 8)
            g_WT[(size_t)(v2 + j) * HIDDEN + h2] = tile[tx][ty + j];
    } else {
        size_t i = (size_t)(blockIdx.x - 8000) * blockDim.x + threadIdx.x;
        float4 w = Wd[i];
        __nv_bfloat16 h0 = __float2bfloat16(w.x), h1 = __float2bfloat16(w.y);
        __nv_bfloat16 h2 = __float2bfloat16(w.z), h3 = __float2bfloat16(w.w);
        __nv_bfloat16 l0 = __float2bfloat16(w.x - __bfloat162float(h0));
        __nv_bfloat16 l1 = __float2bfloat16(w.y - __bfloat162float(h1));
        __nv_bfloat16 l2 = __float2bfloat16(w.z - __bfloat162float(h2));
        __nv_bfloat16 l3 = __float2bfloat16(w.w - __bfloat162float(h3));
        __nv_bfloat162* hi2 = (__nv_bfloat162*)g_Wd_hi;
        __nv_bfloat162* lo2 = (__nv_bfloat162*)g_Wd_lo;
        hi2[i * 2 + 0] = __nv_bfloat162(h0, h1);
        hi2[i * 2 + 1] = __nv_bfloat162(h2, h3);
        lo2[i * 2 + 0] = __nv_bfloat162(l0, l1);
        lo2[i * 2 + 1] = __nv_bfloat162(l2, l3);
    }
}

// ---------------------------------------------------------------------------
// 2) Encode: gather-sum + sigmoid; emit y (fp32 out) and split bf16 copies.
// ---------------------------------------------------------------------------
__global__ void encode_kernel(const int* __restrict__ x_cat,
                              const float* __restrict__ b_enc,
                              float* __restrict__ y_out) {
    int b = blockIdx.x;
    int h = threadIdx.x;
    __shared__ int gidx[N_COLS];
    if (h < N_COLS) gidx[h] = x_cat[b * N_COLS + h] + h * CAT_DIM;
    __syncthreads();
    float acc = b_enc[h];
    #pragma unroll
    for (int i = 0; i < N_COLS; i++)
        acc += g_WT[(size_t)gidx[i] * HIDDEN + h];
    float s = 1.0f / (1.0f + expf(-acc));
    if (y_out) y_out[(size_t)b * HIDDEN + h] = s;
    __nv_bfloat16 hi = __float2bfloat16(s);
    g_y_hi[(size_t)b * HIDDEN + h] = hi;
    g_y_lo[(size_t)b * HIDDEN + h] = __float2bfloat16(s - __bfloat162float(hi));
}

// ---------------------------------------------------------------------------
// 3) Decode GEMM via mma.sync m16n8k16 bf16 (3 accumulating passes).
//    CTA tile 128m x 128n, K=128 resident. 512 threads = 16 warps (4M x 4N),
//    warp tile 32x32 -> 4 warps/SMSP to hide HMMA/LDSM latency.
// ---------------------------------------------------------------------------
#define GM 128
#define GN 128
#define NTHREADS 512

#define OFF_BIAS   0
#define OFF_B_HI   1024
#define OFF_B_LO   (OFF_B_HI + 32768)
#define OFF_A0_HI  (OFF_B_LO + 32768)
#define OFF_A0_LO  (OFF_A0_HI + 32768)
#define OFF_A1_HI  (OFF_A0_LO + 32768)
#define OFF_A1_LO  (OFF_A1_HI + 32768)
#define SMEM_END   (OFF_A1_LO + 32768)
#define SMEM_NEED  (SMEM_END + 1024)

__device__ __forceinline__ uint32_t smem_u32(const void* p) {
    return (uint32_t)__cvta_generic_to_shared(p);
}
// Blocked-atom SW128 byte offset within a [128 rows x 128 k bf16] tile.
__device__ __forceinline__ uint32_t tile_off(int r, int i /*16B chunk 0..15*/) {
    uint32_t off = (uint32_t)(((r >> 3) + ((i >> 3) << 4)) << 10)
                 + (uint32_t)((r & 7) << 7) + (uint32_t)((i & 7) << 4);
    return off ^ ((off >> 3) & 0x70);
}
__device__ __forceinline__ void cp16(uint32_t dst, const void* src) {
    asm volatile("cp.async.cg.shared.global [%0], [%1], 16;"
                 :: "r"(dst), "l"(src) : "memory");
}
__device__ __forceinline__ void ldsm_x4(uint32_t* f, uint32_t addr) {
    asm volatile("ldmatrix.sync.aligned.m8n8.x4.shared.b16 {%0,%1,%2,%3}, [%4];"
                 : "=r"(f[0]), "=r"(f[1]), "=r"(f[2]), "=r"(f[3]) : "r"(addr));
}
__device__ __forceinline__ void mma_bf16(float* c, const uint32_t* a, const uint32_t* b) {
    asm volatile(
        "mma.sync.aligned.m16n8k16.row.col.f32.bf16.bf16.f32 "
        "{%0,%1,%2,%3}, {%4,%5,%6,%7}, {%8,%9}, {%0,%1,%2,%3};"
        : "+f"(c[0]), "+f"(c[1]), "+f"(c[2]), "+f"(c[3])
        : "r"(a[0]), "r"(a[1]), "r"(a[2]), "r"(a[3]), "r"(b[0]), "r"(b[1]));
}

__global__ __launch_bounds__(NTHREADS, 1)
void decode_gemm_mma(const float* __restrict__ bias, float* __restrict__ C,
                     int mBlocks) {
    extern __shared__ char smem_raw[];
    uint32_t raw = smem_u32(smem_raw);
    uint32_t base = (raw + 1023u) & ~1023u;
    char* sm = smem_raw + (base - raw);

    const int tid = threadIdx.x;
    const int wid = tid >> 5, lane = tid & 31;
    const int warpM = wid >> 2;          // 0..3
    const int warpN = wid & 3;           // 0..3
    const int v0 = blockIdx.x * GN;
    const int mPer = mBlocks / gridDim.y;
    const int mBeg = blockIdx.y * mPer;

    // bias stage
    if (tid < GN) *(float*)(sm + OFF_BIAS + tid * 4) = bias[v0 + tid];

    // B tile (hi+lo), swizzled (once per CTA). 2048 uint4 per tile.
    #pragma unroll
    for (int it = 0; it < 4; it++) {
        int idx = it * NTHREADS + tid;
        int r = idx >> 4, i = idx & 15;
        uint32_t so = tile_off(r, i);
        *(uint4*)(sm + OFF_B_HI + so) = ((const uint4*)(g_Wd_hi + (size_t)(v0 + r) * HIDDEN))[i];
        *(uint4*)(sm + OFF_B_LO + so) = ((const uint4*)(g_Wd_lo + (size_t)(v0 + r) * HIDDEN))[i];
    }

    // prefetch A tile 0 into buffer 0 (cp.async)
    {
        const int m0 = mBeg * GM;
        #pragma unroll
        for (int it = 0; it < 4; it++) {
            int idx = it * NTHREADS + tid;
            int r = idx >> 4, i = idx & 15;
            uint32_t so = tile_off(r, i);
            cp16(base + OFF_A0_HI + so, (const char*)(g_y_hi + (size_t)(m0 + r) * HIDDEN) + i * 16);
            cp16(base + OFF_A0_LO + so, (const char*)(g_y_lo + (size_t)(m0 + r) * HIDDEN) + i * 16);
        }
        asm volatile("cp.async.commit_group;" ::: "memory");
    }

    // per-thread ldmatrix base addresses
    const int aRow = warpM * 32 + (lane & 15);                      // + mt*16
    const int aChk = (lane >> 4);                                   // + ks*2
    const int bRow = warpN * 32 + ((lane >> 4) << 3) + (lane & 7);  // + bt*16
    const int bChk = (lane >> 3) & 1;                               // + ks*2

    const uint32_t AOFF[2][2] = {{base + OFF_A0_HI, base + OFF_A0_LO},
                                 {base + OFF_A1_HI, base + OFF_A1_LO}};

    for (int mi = 0; mi < mPer; mi++) {
        const int m0 = (mBeg + mi) * GM;
        const int buf = mi & 1;

        asm volatile("cp.async.wait_group 0;" ::: "memory");
        __syncthreads();

        // prefetch next A tile into the other buffer
        if (mi + 1 < mPer) {
            const int m1 = (mBeg + mi + 1) * GM;
            const uint32_t hiDst = AOFF[buf ^ 1][0], loDst = AOFF[buf ^ 1][1];
            #pragma unroll
            for (int it = 0; it < 4; it++) {
                int idx = it * NTHREADS + tid;
                int r = idx >> 4, i = idx & 15;
                uint32_t so = tile_off(r, i);
                cp16(hiDst + so, (const char*)(g_y_hi + (size_t)(m1 + r) * HIDDEN) + i * 16);
                cp16(loDst + so, (const char*)(g_y_lo + (size_t)(m1 + r) * HIDDEN) + i * 16);
            }
            asm volatile("cp.async.commit_group;" ::: "memory");
        }

        float acc[2][4][4];
        #pragma unroll
        for (int mt = 0; mt < 2; mt++)
            #pragma unroll
            for (int nt = 0; nt < 4; nt++)
                #pragma unroll
                for (int q = 0; q < 4; q++)
                    acc[mt][nt][q] = 0.0f;

        const uint32_t aHi = AOFF[buf][0], aLo = AOFF[buf][1];

        #pragma unroll
        for (int ks = 0; ks < 8; ks++) {
            uint32_t ah[2][4], al[2][4];
            #pragma unroll
            for (int mt = 0; mt < 2; mt++) {
                uint32_t so = tile_off(aRow + mt * 16, ks * 2 + aChk);
                ldsm_x4(ah[mt], aHi + so);
                ldsm_x4(al[mt], aLo + so);
            }
            uint32_t bh[4][2], bl[4][2];
            #pragma unroll
            for (int bt = 0; bt < 2; bt++) {
                uint32_t so = tile_off(bRow + bt * 16, ks * 2 + bChk);
                uint32_t fh[4], fl[4];
                ldsm_x4(fh, base + OFF_B_HI + so);
                ldsm_x4(fl, base + OFF_B_LO + so);
                bh[bt * 2 + 0][0] = fh[0]; bh[bt * 2 + 0][1] = fh[1];
                bh[bt * 2 + 1][0] = fh[2]; bh[bt * 2 + 1][1] = fh[3];
                bl[bt * 2 + 0][0] = fl[0]; bl[bt * 2 + 0][1] = fl[1];
                bl[bt * 2 + 1][0] = fl[2]; bl[bt * 2 + 1][1] = fl[3];
            }
            #pragma unroll
            for (int mt = 0; mt < 2; mt++)
                #pragma unroll
                for (int nt = 0; nt < 4; nt++) {
                    mma_bf16(acc[mt][nt], ah[mt], bh[nt]);
                    mma_bf16(acc[mt][nt], al[mt], bh[nt]);
                    mma_bf16(acc[mt][nt], ah[mt], bl[nt]);
                }
        }

        // epilogue: bias + float2 stores
        const int cCol = warpN * 32 + 2 * (lane & 3);
        const int cRow = warpM * 32 + (lane >> 2);
        #pragma unroll
        for (int mt = 0; mt < 2; mt++) {
            #pragma unroll
            for (int nt = 0; nt < 4; nt++) {
                int col = cCol + nt * 8;
                float bx = *(float*)(sm + OFF_BIAS + col * 4);
                float by = *(float*)(sm + OFF_BIAS + (col + 1) * 4);
                size_t r0 = (size_t)(m0 + cRow + mt * 16) * TOTAL + v0 + col;
                size_t r1 = r0 + 8 * TOTAL;
                float2 o0 = make_float2(acc[mt][nt][0] + bx, acc[mt][nt][1] + by);
                float2 o1 = make_float2(acc[mt][nt][2] + bx, acc[mt][nt][3] + by);
                *(float2*)&C[r0] = o0;
                *(float2*)&C[r1] = o1;
            }
        }
        __syncthreads();   // protect smem A buffer reuse ordering
    }
}

// ---------------------------------------------------------------------------
// Launch
// ---------------------------------------------------------------------------
extern "C" void kernel_launch(void* const* d_in, const int* in_sizes, int n_in,
                              void* d_out, int out_size) {
    const int*   x_cat = (const int*)d_in[0];
    const float* W_enc = (const float*)d_in[1];
    const float* b_enc = (const float*)d_in[2];
    const float* W_dec = (const float*)d_in[3];
    const float* b_dec = (const float*)d_in[4];

    int B = in_sizes[0] / N_COLS;
    if (B > MAX_B) B = MAX_B;

    float* out = (float*)d_out;
    size_t yElems = (size_t)B * HIDDEN;
    size_t zElems = (size_t)B * TOTAL;
    float* yOut;
    float* zOut;
    if ((long long)out_size == (long long)(yElems + zElems)) {
        yOut = out; zOut = out + yElems;
    } else {
        yOut = nullptr; zOut = out;
    }

    cudaFuncSetAttribute(decode_gemm_mma, cudaFuncAttributeMaxDynamicSharedMemorySize, SMEM_NEED);

    prep_kernel<<<16000, 256>>>(W_enc, (const float4*)W_dec);
    encode_kernel<<<B, HIDDEN>>>(x_cat, b_enc, yOut);

    int mBlocks = B / GM;                       // 16
    int ySplit = (mBlocks % 2 == 0) ? 2 : 1;    // 1000 CTAs
    decode_gemm_mma<<<dim3(TOTAL / GN, ySplit), NTHREADS, SMEM_NEED>>>(b_dec, zOut, mBlocks);
}